// round 10
// baseline (speedup 1.0000x reference)
#include <cuda_runtime.h>

// Problem dims  (V, E, H, N, L = 32000, 512, 1024, 16, 128)
#define VV 32000
#define NB 16
#define LL 128
#define EE 512
#define HH 1024
#define G4 4096
#define MM (NB*LL)
#define RB 128           // persistent recurrence CTAs (1/SM, co-resident)
#define NGRP 8           // barrier tree groups
#define GSZ  16          // CTAs per group

// Scratch
__device__ __align__(16) float g_X0[(size_t)MM * G4];   // 33.5 MB
__device__ __align__(16) float g_X1[(size_t)MM * G4];   // 33.5 MB
__device__ __align__(16) float g_H0[(size_t)MM * HH];   //  8.4 MB
__device__ __align__(16) float g_h[2][NB * HH];         // h double buffer, [k][b]
// Two-level barrier state: group counters on distinct 256B-spaced L2 lines.
__device__ __align__(16) unsigned g_grp[NGRP * 64];     // use index i*64
__device__ unsigned g_root    = 0;
__device__ unsigned g_bar_gen = 0;

__device__ __forceinline__ float sigf(float x) { return 1.0f / (1.0f + __expf(-x)); }

// ---- packed f32x2 helpers -------------------------------------------------
typedef unsigned long long ull;

__device__ __forceinline__ ull pack2(float x) {
    ull r; asm("mov.b64 %0, {%1, %1};" : "=l"(r) : "f"(x)); return r;
}
__device__ __forceinline__ void ffma2(ull& d, ull a, ull b) {
    asm("fma.rn.f32x2 %0, %1, %2, %0;" : "+l"(d) : "l"(a), "l"(b));
}
__device__ __forceinline__ ull fadd2(ull a, ull b) {
    ull d; asm("add.rn.f32x2 %0, %1, %2;" : "=l"(d) : "l"(a), "l"(b)); return d;
}
__device__ __forceinline__ void unpack2(ull v, float& lo, float& hi) {
    asm("mov.b64 {%0, %1}, %2;" : "=f"(lo), "=f"(hi) : "l"(v));
}

// ---- grid barrier: two-level atomic tree, round-6 primitives only --------
// Fan-in: 16 atomics/group across 8 parallel L2 lines, then 8 to root.
// Release: root completer resets counters (atomicExch), fences, bumps gen;
// all other CTA-leaders equality-spin on gen (proven for 128 spinners in R6).
__device__ __forceinline__ void grid_sync() {
    __threadfence();
    __syncthreads();
    if (threadIdx.x == 0) {
        unsigned gen = ((volatile unsigned*)&g_bar_gen)[0];
        const int g = blockIdx.x >> 4;          // 16 CTAs per group
        unsigned a = atomicAdd(&g_grp[g * 64], 1u);
        if (a == GSZ - 1) {
            unsigned r = atomicAdd(&g_root, 1u);
            if (r == NGRP - 1) {
                // quiescent: everyone else spins on gen
#pragma unroll
                for (int i = 0; i < NGRP; i++) atomicExch(&g_grp[i * 64], 0u);
                atomicExch(&g_root, 0u);
                __threadfence();
                atomicExch(&g_bar_gen, gen + 1u);
            } else {
                while (((volatile unsigned*)&g_bar_gen)[0] == gen) { }
            }
        } else {
            while (((volatile unsigned*)&g_bar_gen)[0] == gen) { }
        }
        __threadfence();
    }
    __syncthreads();
}

// ---------------------------------------------------------------------------
// GEMM  C[m][r] = sum_k A[m][k]*B[r][k] + bias[r];  A gathered via tokens.
// Tile 128x128, 256 threads, 8x8/thread, K-tile 16, DOUBLE-BUFFERED smem.
// ---------------------------------------------------------------------------
template <int K>
__global__ __launch_bounds__(256) void gemm_nt(
    const float* __restrict__ Aext,
    const int*   __restrict__ tokens,
    const float* __restrict__ B,
    const float* __restrict__ bias,
    int a_sel, int c_sel)
{
    __shared__ __align__(16) float As[2][16][132];
    __shared__ __align__(16) float Bs[2][16][132];

    float* C = c_sel ? g_X1 : g_X0;
    const int bm = blockIdx.y, br = blockIdx.x;
    const int tid = threadIdx.x;
    const int tx = tid & 15, ty = tid >> 4;

    const int r0 = tid >> 2;
    const int r1 = r0 + 64;
    const int kq = (tid & 3) << 2;

    const float* arow0;
    const float* arow1;
    if (tokens) {
        int gm0 = bm * 128 + r0, gm1 = bm * 128 + r1;
        int t0 = tokens[(gm0 & (NB - 1)) * LL + (gm0 >> 4)];
        int t1 = tokens[(gm1 & (NB - 1)) * LL + (gm1 >> 4)];
        t0 = min(max(t0, 0), VV - 1);
        t1 = min(max(t1, 0), VV - 1);
        arow0 = Aext + (size_t)t0 * K;
        arow1 = Aext + (size_t)t1 * K;
    } else {
        const float* A = a_sel ? g_H0 : Aext;
        arow0 = A + (size_t)(bm * 128 + r0) * K;
        arow1 = A + (size_t)(bm * 128 + r1) * K;
    }
    const float* brow0 = B + (size_t)(br * 128 + r0) * K;
    const float* brow1 = B + (size_t)(br * 128 + r1) * K;

    float acc[8][8];
#pragma unroll
    for (int i = 0; i < 8; i++)
#pragma unroll
        for (int jj = 0; jj < 8; jj++) acc[i][jj] = 0.0f;

    // prologue: tile 0
    {
        float4 av0 = *(const float4*)(arow0 + kq);
        float4 av1 = *(const float4*)(arow1 + kq);
        float4 bv0 = *(const float4*)(brow0 + kq);
        float4 bv1 = *(const float4*)(brow1 + kq);
        As[0][kq + 0][r0] = av0.x; As[0][kq + 1][r0] = av0.y; As[0][kq + 2][r0] = av0.z; As[0][kq + 3][r0] = av0.w;
        As[0][kq + 0][r1] = av1.x; As[0][kq + 1][r1] = av1.y; As[0][kq + 2][r1] = av1.z; As[0][kq + 3][r1] = av1.w;
        Bs[0][kq + 0][r0] = bv0.x; Bs[0][kq + 1][r0] = bv0.y; Bs[0][kq + 2][r0] = bv0.z; Bs[0][kq + 3][r0] = bv0.w;
        Bs[0][kq + 0][r1] = bv1.x; Bs[0][kq + 1][r1] = bv1.y; Bs[0][kq + 2][r1] = bv1.z; Bs[0][kq + 3][r1] = bv1.w;
    }
    __syncthreads();

    int cur = 0;
#pragma unroll 1
    for (int k0 = 0; k0 < K; k0 += 16) {
        const bool more = (k0 + 16) < K;
        float4 nav0, nav1, nbv0, nbv1;
        if (more) {                       // issue next tile's LDGs early
            nav0 = *(const float4*)(arow0 + k0 + 16 + kq);
            nav1 = *(const float4*)(arow1 + k0 + 16 + kq);
            nbv0 = *(const float4*)(brow0 + k0 + 16 + kq);
            nbv1 = *(const float4*)(brow1 + k0 + 16 + kq);
        }

#pragma unroll
        for (int kk = 0; kk < 16; kk++) {
            float4 a0 = *(const float4*)&As[cur][kk][ty * 8];
            float4 a1 = *(const float4*)&As[cur][kk][ty * 8 + 4];
            float4 b0 = *(const float4*)&Bs[cur][kk][tx * 8];
            float4 b1 = *(const float4*)&Bs[cur][kk][tx * 8 + 4];
            float a[8] = {a0.x, a0.y, a0.z, a0.w, a1.x, a1.y, a1.z, a1.w};
            float b[8] = {b0.x, b0.y, b0.z, b0.w, b1.x, b1.y, b1.z, b1.w};
#pragma unroll
            for (int i = 0; i < 8; i++)
#pragma unroll
                for (int jj = 0; jj < 8; jj++)
                    acc[i][jj] = fmaf(a[i], b[jj], acc[i][jj]);
        }

        if (more) {
            int nxt = cur ^ 1;
            As[nxt][kq + 0][r0] = nav0.x; As[nxt][kq + 1][r0] = nav0.y; As[nxt][kq + 2][r0] = nav0.z; As[nxt][kq + 3][r0] = nav0.w;
            As[nxt][kq + 0][r1] = nav1.x; As[nxt][kq + 1][r1] = nav1.y; As[nxt][kq + 2][r1] = nav1.z; As[nxt][kq + 3][r1] = nav1.w;
            Bs[nxt][kq + 0][r0] = nbv0.x; Bs[nxt][kq + 1][r0] = nbv0.y; Bs[nxt][kq + 2][r0] = nbv0.z; Bs[nxt][kq + 3][r0] = nbv0.w;
            Bs[nxt][kq + 0][r1] = nbv1.x; Bs[nxt][kq + 1][r1] = nbv1.y; Bs[nxt][kq + 2][r1] = nbv1.z; Bs[nxt][kq + 3][r1] = nbv1.w;
            __syncthreads();
            cur = nxt;
        }
    }

    const int gc = br * 128 + tx * 8;
    float bia[8];
#pragma unroll
    for (int jj = 0; jj < 8; jj++) bia[jj] = bias[gc + jj];
#pragma unroll
    for (int i = 0; i < 8; i++) {
        int gm = bm * 128 + ty * 8 + i;
        float4 o0, o1;
        o0.x = acc[i][0] + bia[0]; o0.y = acc[i][1] + bia[1];
        o0.z = acc[i][2] + bia[2]; o0.w = acc[i][3] + bia[3];
        o1.x = acc[i][4] + bia[4]; o1.y = acc[i][5] + bia[5];
        o1.z = acc[i][6] + bia[6]; o1.w = acc[i][7] + bia[7];
        *(float4*)(C + (size_t)gm * G4 + gc)     = o0;
        *(float4*)(C + (size_t)gm * G4 + gc + 4) = o1;
    }
}

// ---------------------------------------------------------------------------
// Persistent LSTM recurrence: 128 CTAs x 256 thr, all 128 steps in one launch.
// ---------------------------------------------------------------------------
__global__ __launch_bounds__(256) void lstm_rec(
    const float* __restrict__ Whh,
    float* __restrict__ Out,
    int xsel, int mode)
{
    extern __shared__ __align__(16) float sm[];
    float* ws = sm;                    // 32768 floats: ws[w][g][k]
    float* hs = sm + 32768;            // 20480 floats: h padded [k][20]
    float* gs = hs + 20480;            // 512: reduced gates
    float* xs = gs + 512;              // 512: staged X slice

    const float* Xg = xsel ? g_X1 : g_X0;
    const int tid = threadIdx.x, lane = tid & 31, wp = tid >> 5;
    const int j = blockIdx.x * 8 + wp;

    // ---- preload weight slice (128 KB) into smem ----
    for (int i = tid; i < 8192; i += 256) {
        int wgk = i * 4;
        int w_ = wgk >> 12, g = (wgk >> 10) & 3, k = wgk & 1023;
        ((float4*)ws)[i] = *(const float4*)(Whh + (size_t)(g * HH + blockIdx.x * 8 + w_) * HH + k);
    }
    for (int i = tid; i < 20480; i += 256) hs[i] = 0.0f;

    float creg = 0.0f;
    __syncthreads();

    for (int t = 0; t < LL; t++) {
        // prefetch X gate slice early (latency overlaps h staging)
        float2 xv;
        int xb = tid >> 4, xr = tid & 15, xg = xr >> 2, xj2 = (xr & 3) << 1;
        xv = *(const float2*)(Xg + (size_t)(t * NB + xb) * G4 + xg * HH + blockIdx.x * 8 + xj2);

        if (t > 0) {
            const float4* src = (const float4*)g_h[t & 1];
            for (int i = tid; i < 4096; i += 256) {
                float4 hv = __ldcg(src + i);
                int k = i >> 2, b4 = (i & 3) << 2;
                *(float4*)(hs + k * 20 + b4) = hv;
            }
        }
        xs[xj2 * 64 + xg * 16 + xb]       = xv.x;
        xs[(xj2 + 1) * 64 + xg * 16 + xb] = xv.y;
        __syncthreads();

        // ---- gate GEMV: acc[g][p] packs batches (2p, 2p+1) ----
        ull acc[4][8];
#pragma unroll
        for (int g = 0; g < 4; g++)
#pragma unroll
            for (int p = 0; p < 8; p++) acc[g][p] = 0ull;

        const float* wr = ws + wp * 4096;
#pragma unroll 8
        for (int i = 0; i < 32; i++) {
            int k = i * 32 + lane;
            ull W0 = pack2(wr[k]);
            ull W1 = pack2(wr[1024 + k]);
            ull W2 = pack2(wr[2048 + k]);
            ull W3 = pack2(wr[3072 + k]);
            const ulonglong2* hp = (const ulonglong2*)(hs + k * 20);
            ulonglong2 ha = hp[0], hb = hp[1], hc = hp[2], hd = hp[3];
            ffma2(acc[0][0], W0, ha.x); ffma2(acc[0][1], W0, ha.y);
            ffma2(acc[0][2], W0, hb.x); ffma2(acc[0][3], W0, hb.y);
            ffma2(acc[0][4], W0, hc.x); ffma2(acc[0][5], W0, hc.y);
            ffma2(acc[0][6], W0, hd.x); ffma2(acc[0][7], W0, hd.y);
            ffma2(acc[1][0], W1, ha.x); ffma2(acc[1][1], W1, ha.y);
            ffma2(acc[1][2], W1, hb.x); ffma2(acc[1][3], W1, hb.y);
            ffma2(acc[1][4], W1, hc.x); ffma2(acc[1][5], W1, hc.y);
            ffma2(acc[1][6], W1, hd.x); ffma2(acc[1][7], W1, hd.y);
            ffma2(acc[2][0], W2, ha.x); ffma2(acc[2][1], W2, ha.y);
            ffma2(acc[2][2], W2, hb.x); ffma2(acc[2][3], W2, hb.y);
            ffma2(acc[2][4], W2, hc.x); ffma2(acc[2][5], W2, hc.y);
            ffma2(acc[2][6], W2, hd.x); ffma2(acc[2][7], W2, hd.y);
            ffma2(acc[3][0], W3, ha.x); ffma2(acc[3][1], W3, ha.y);
            ffma2(acc[3][2], W3, hb.x); ffma2(acc[3][3], W3, hb.y);
            ffma2(acc[3][4], W3, hc.x); ffma2(acc[3][5], W3, hc.y);
            ffma2(acc[3][6], W3, hd.x); ffma2(acc[3][7], W3, hd.y);
        }

        // ---- multi-value butterfly reduction across lanes ----
        ull* v = &acc[0][0];
#pragma unroll
        for (int m = 16; m >= 1; m >>= 1) {
            int half = m;
#pragma unroll
            for (int i = 0; i < 16; i++) {
                if (i < half) {
                    ull send = (lane & m) ? v[i] : v[i + half];
                    ull recv = __shfl_xor_sync(0xffffffffu, send, m);
                    ull keep = (lane & m) ? v[i + half] : v[i];
                    v[i] = fadd2(keep, recv);
                }
            }
        }
        {
            int g = lane >> 3, p = lane & 7;
            float lo, hi;
            unpack2(v[0], lo, hi);
            gs[wp * 64 + g * 16 + 2 * p]     = lo;
            gs[wp * 64 + g * 16 + 2 * p + 1] = hi;
        }
        __syncwarp();

        if (lane < 16) {
            const int b = lane;
            float gi = gs[wp * 64 +  0 + b] + xs[wp * 64 +  0 + b];
            float gf = gs[wp * 64 + 16 + b] + xs[wp * 64 + 16 + b];
            float gg = gs[wp * 64 + 32 + b] + xs[wp * 64 + 32 + b];
            float go = gs[wp * 64 + 48 + b] + xs[wp * 64 + 48 + b];
            float c = sigf(gf) * creg + sigf(gi) * tanhf(gg);
            float h = sigf(go) * tanhf(c);
            creg = c;
            __stcg(&g_h[(t + 1) & 1][j * 16 + b], h);
            if (mode == 0)
                g_H0[(size_t)(t * NB + b) * HH + j] = h;
            else
                Out[(size_t)b * (LL * HH) + (size_t)t * HH + j] = h;
        }

        if (t != LL - 1) grid_sync();
    }
}

// ---------------------------------------------------------------------------
extern "C" void kernel_launch(void* const* d_in, const int* in_sizes, int n_in,
                              void* d_out, int out_size)
{
    const int*   x    = nullptr;
    const float* emb  = nullptr;
    const float* wih0 = nullptr;
    const float* bias_[2] = {nullptr, nullptr};
    const float* w4[3] = {nullptr, nullptr, nullptr};
    int nbias = 0, nw = 0;
    for (int i = 0; i < n_in; i++) {
        long long sz = in_sizes[i];
        if (sz == (long long)NB * LL)             x = (const int*)d_in[i];
        else if (sz == (long long)VV * EE)        emb = (const float*)d_in[i];
        else if (sz == (long long)G4 * EE)        wih0 = (const float*)d_in[i];
        else if (sz == (long long)G4)             { if (nbias < 2) bias_[nbias++] = (const float*)d_in[i]; }
        else if (sz == (long long)G4 * HH)        { if (nw < 3) w4[nw++] = (const float*)d_in[i]; }
    }
    if (!x || !emb || !wih0 || nbias < 2 || nw < 3) {
        x = (const int*)d_in[0];
        emb = (const float*)d_in[1];
        wih0 = (const float*)d_in[2];
        w4[0] = (const float*)d_in[3];
        bias_[0] = (const float*)d_in[4];
        w4[1] = (const float*)d_in[5];
        w4[2] = (const float*)d_in[6];
        bias_[1] = (const float*)d_in[7];
    }
    const float* whh0 = w4[0];
    const float* b0   = bias_[0];
    const float* wih1 = w4[1];
    const float* whh1 = w4[2];
    const float* b1   = bias_[1];
    float* out = (float*)d_out;

    const int smem_rec = (32768 + 20480 + 512 + 512) * (int)sizeof(float);  // 217088 B
    cudaFuncSetAttribute(lstm_rec, cudaFuncAttributeMaxDynamicSharedMemorySize, smem_rec);

    dim3 ggrid(G4 / 128, MM / 128);  // (32, 16)

    gemm_nt<EE><<<ggrid, 256>>>(emb, x, wih0, b0, 0, 0);
    lstm_rec<<<RB, 256, smem_rec>>>(whh0, out, 0, 0);
    gemm_nt<HH><<<ggrid, 256>>>(emb, nullptr, wih1, b1, 1, 1);
    lstm_rec<<<RB, 256, smem_rec>>>(whh1, out, 1, 1);
}

// round 11
// speedup vs baseline: 1.0426x; 1.0426x over previous
#include <cuda_runtime.h>
#include <cuda_bf16.h>

// Problem dims  (V, E, H, N, L = 32000, 512, 1024, 16, 128)
#define VV 32000
#define NB 16
#define LL 128
#define EE 512
#define HH 1024
#define G4 4096
#define MM (NB*LL)
#define RB 128           // persistent recurrence CTAs (1/SM, co-resident)
#define NGRP 8
#define GSZ  16

// Scratch
__device__ __align__(16) float g_X0[(size_t)MM * G4];
__device__ __align__(16) float g_X1[(size_t)MM * G4];
__device__ __align__(16) float g_H0[(size_t)MM * HH];
__device__ __align__(16) float g_h[2][NB * HH];
// Monotonic barrier state: NEVER reset; all values derived from atomic returns.
__device__ __align__(16) unsigned g_grpm[NGRP * 64];   // group counters, 256B apart
__device__ unsigned g_rootm = 0;
__device__ unsigned g_genm  = 0;

__device__ __forceinline__ float sigf(float x) { return 1.0f / (1.0f + __expf(-x)); }

// ---- packed f32x2 helpers -------------------------------------------------
typedef unsigned long long ull;

__device__ __forceinline__ ull pack2(float x) {
    ull r; asm("mov.b64 %0, {%1, %1};" : "=l"(r) : "f"(x)); return r;
}
__device__ __forceinline__ void ffma2(ull& d, ull a, ull b) {
    asm("fma.rn.f32x2 %0, %1, %2, %0;" : "+l"(d) : "l"(a), "l"(b));
}
__device__ __forceinline__ ull fadd2(ull a, ull b) {
    ull d; asm("add.rn.f32x2 %0, %1, %2;" : "=l"(d) : "l"(a), "l"(b)); return d;
}
__device__ __forceinline__ void unpack2(ull v, float& lo, float& hi) {
    asm("mov.b64 {%0, %1}, %2;" : "=f"(lo), "=f"(hi) : "l"(v));
}

// ---- grid barrier: monotonic two-level tree, NO resets --------------------
// Instance n derived from arrival return (old>>4). Group completer
// (old&15)==15 arrives at root; root completer (ro&7)==7 bumps gen.
// Everyone else spins until gen >= n+1 (signed wrap-safe).
__device__ __forceinline__ void grid_sync() {
    __threadfence();
    __syncthreads();
    if (threadIdx.x == 0) {
        const int g = blockIdx.x >> 4;
        unsigned old = atomicAdd(&g_grpm[g * 64], 1u);
        unsigned n = old >> 4;                  // barrier instance
        bool released = false;
        if ((old & 15u) == 15u) {
            __threadfence();
            unsigned ro = atomicAdd(&g_rootm, 1u);
            if ((ro & 7u) == 7u) {
                __threadfence();
                atomicAdd(&g_genm, 1u);         // release: gen -> n+1
                released = true;
            }
        }
        if (!released) {
            while ((int)(((volatile unsigned*)&g_genm)[0] - (n + 1u)) < 0) { }
        }
        __threadfence();
    }
    __syncthreads();
}

// ---- bf16 hi/lo split pack ------------------------------------------------
__device__ __forceinline__ void cvt_pair(float x0, float x1, unsigned& hi, unsigned& lo) {
    __nv_bfloat16 h0 = __float2bfloat16(x0);
    __nv_bfloat16 h1 = __float2bfloat16(x1);
    float r0 = x0 - __bfloat162float(h0);
    float r1 = x1 - __bfloat162float(h1);
    __nv_bfloat162 hp = __halves2bfloat162(h0, h1);
    __nv_bfloat162 lp = __halves2bfloat162(__float2bfloat16(r0), __float2bfloat16(r1));
    hi = *(unsigned*)&hp;
    lo = *(unsigned*)&lp;
}

#define MMA4(d, a, b0r, b1r) \
    asm volatile("mma.sync.aligned.m16n8k16.row.col.f32.bf16.bf16.f32 " \
        "{%0,%1,%2,%3}, {%4,%5,%6,%7}, {%8,%9}, {%0,%1,%2,%3};" \
        : "+f"((d)[0]), "+f"((d)[1]), "+f"((d)[2]), "+f"((d)[3]) \
        : "r"((a)[0]), "r"((a)[1]), "r"((a)[2]), "r"((a)[3]), "r"(b0r), "r"(b1r))

// ---------------------------------------------------------------------------
// Tensor-core GEMM: C[m][r] = sum_k A[m][k]*B[r][k] + bias[r].
// bf16 hi/lo split, 3 passes (hi*hi + hi*lo + lo*hi), fp32 accum.
// Tile 128x128, 8 warps (4 along m x 2 along n), warp tile 32m x 64n.
// Both operands k-contiguous -> direct lds.b32 fragment loads, no ldmatrix.
// ---------------------------------------------------------------------------
template <int K>
__global__ __launch_bounds__(256) void gemm_tc(
    const float* __restrict__ Aext,
    const int*   __restrict__ tokens,
    const float* __restrict__ Bw,
    const float* __restrict__ bias,
    int a_sel, int c_sel)
{
    __shared__ __align__(16) unsigned sAhi[128 * 9];
    __shared__ __align__(16) unsigned sAlo[128 * 9];
    __shared__ __align__(16) unsigned sBhi[128 * 9];
    __shared__ __align__(16) unsigned sBlo[128 * 9];

    float* C = c_sel ? g_X1 : g_X0;
    const int bm = blockIdx.y, br = blockIdx.x;
    const int tid = threadIdx.x, lane = tid & 31, wid = tid >> 5;

    // loader: thread t handles row ra = t>>1, k-offset kc = (t&1)*8 (8 floats)
    const int ra = tid >> 1;
    const int kc = (tid & 1) * 8;

    const float* arow;
    if (tokens) {
        int gm = bm * 128 + ra;
        int tok = tokens[(gm & (NB - 1)) * LL + (gm >> 4)];
        tok = min(max(tok, 0), VV - 1);
        arow = Aext + (size_t)tok * K + kc;
    } else {
        const float* A = a_sel ? g_H0 : Aext;
        arow = A + (size_t)(bm * 128 + ra) * K + kc;
    }
    const float* brow = Bw + (size_t)(br * 128 + ra) * K + kc;

    const int wm = (wid & 3) * 32;      // warp m offset
    const int wn = (wid >> 2) * 64;     // warp n offset
    const int gid = lane >> 2, qc = lane & 3;

    float acc[2][8][4];
#pragma unroll
    for (int mi = 0; mi < 2; mi++)
#pragma unroll
        for (int j = 0; j < 8; j++)
#pragma unroll
            for (int e = 0; e < 4; e++) acc[mi][j][e] = 0.0f;

    // helper lambda-ish: convert 8 floats -> 4 hi/lo u32 pairs and store
#define STCVT(dsthi, dstlo, v0, v1)  do {                                   \
        unsigned h_, l_;                                                    \
        cvt_pair((v0).x, (v0).y, h_, l_); dsthi[ra*9 + kc/2 + 0] = h_; dstlo[ra*9 + kc/2 + 0] = l_; \
        cvt_pair((v0).z, (v0).w, h_, l_); dsthi[ra*9 + kc/2 + 1] = h_; dstlo[ra*9 + kc/2 + 1] = l_; \
        cvt_pair((v1).x, (v1).y, h_, l_); dsthi[ra*9 + kc/2 + 2] = h_; dstlo[ra*9 + kc/2 + 2] = l_; \
        cvt_pair((v1).z, (v1).w, h_, l_); dsthi[ra*9 + kc/2 + 3] = h_; dstlo[ra*9 + kc/2 + 3] = l_; \
    } while (0)

    // prologue: tile 0
    {
        float4 av0 = *(const float4*)(arow);
        float4 av1 = *(const float4*)(arow + 4);
        float4 bv0 = *(const float4*)(brow);
        float4 bv1 = *(const float4*)(brow + 4);
        STCVT(sAhi, sAlo, av0, av1);
        STCVT(sBhi, sBlo, bv0, bv1);
    }
    __syncthreads();

#pragma unroll 1
    for (int k0 = 0; k0 < K; k0 += 16) {
        const bool more = (k0 + 16) < K;
        float4 nav0, nav1, nbv0, nbv1;
        if (more) {
            nav0 = *(const float4*)(arow + k0 + 16);
            nav1 = *(const float4*)(arow + k0 + 20);
            nbv0 = *(const float4*)(brow + k0 + 16);
            nbv1 = *(const float4*)(brow + k0 + 20);
        }

        // A fragments for both m16 tiles (hi and lo)
        unsigned ahi[2][4], alo[2][4];
#pragma unroll
        for (int mi = 0; mi < 2; mi++) {
            int r0 = (wm + mi * 16 + gid) * 9;
            int r8 = r0 + 8 * 9;
            ahi[mi][0] = sAhi[r0 + qc];     ahi[mi][1] = sAhi[r8 + qc];
            ahi[mi][2] = sAhi[r0 + qc + 4]; ahi[mi][3] = sAhi[r8 + qc + 4];
            alo[mi][0] = sAlo[r0 + qc];     alo[mi][1] = sAlo[r8 + qc];
            alo[mi][2] = sAlo[r0 + qc + 4]; alo[mi][3] = sAlo[r8 + qc + 4];
        }

#pragma unroll
        for (int j = 0; j < 8; j++) {
            int rb = (wn + j * 8 + gid) * 9;
            unsigned bh0 = sBhi[rb + qc], bh1 = sBhi[rb + qc + 4];
            unsigned bl0 = sBlo[rb + qc], bl1 = sBlo[rb + qc + 4];
#pragma unroll
            for (int mi = 0; mi < 2; mi++) {
                MMA4(acc[mi][j], ahi[mi], bh0, bh1);
                MMA4(acc[mi][j], ahi[mi], bl0, bl1);
                MMA4(acc[mi][j], alo[mi], bh0, bh1);
            }
        }

        if (more) {
            __syncthreads();           // all fragment reads done
            STCVT(sAhi, sAlo, nav0, nav1);
            STCVT(sBhi, sBlo, nbv0, nbv1);
            __syncthreads();
        }
    }
#undef STCVT

    // epilogue: c0,c1 = (row gid, cols 2qc,2qc+1); c2,c3 = row gid+8
#pragma unroll
    for (int j = 0; j < 8; j++) {
        int gc = br * 128 + wn + j * 8 + qc * 2;
        float b0v = bias[gc], b1v = bias[gc + 1];
#pragma unroll
        for (int mi = 0; mi < 2; mi++) {
            int gm0 = bm * 128 + wm + mi * 16 + gid;
            float2 o0 = make_float2(acc[mi][j][0] + b0v, acc[mi][j][1] + b1v);
            float2 o1 = make_float2(acc[mi][j][2] + b0v, acc[mi][j][3] + b1v);
            *(float2*)(C + (size_t)gm0 * G4 + gc)       = o0;
            *(float2*)(C + (size_t)(gm0 + 8) * G4 + gc) = o1;
        }
    }
}

// ---------------------------------------------------------------------------
// Persistent LSTM recurrence: 128 CTAs x 256 thr, all 128 steps in one launch.
// ---------------------------------------------------------------------------
__global__ __launch_bounds__(256) void lstm_rec(
    const float* __restrict__ Whh,
    float* __restrict__ Out,
    int xsel, int mode)
{
    extern __shared__ __align__(16) float sm[];
    float* ws = sm;                    // 32768 floats: ws[w][g][k]
    float* hs = sm + 32768;            // 20480 floats: h padded [k][20]
    float* gs = hs + 20480;            // 512: reduced gates
    float* xs = gs + 512;              // 512: staged X slice

    const float* Xg = xsel ? g_X1 : g_X0;
    const int tid = threadIdx.x, lane = tid & 31, wp = tid >> 5;
    const int j = blockIdx.x * 8 + wp;

    for (int i = tid; i < 8192; i += 256) {
        int wgk = i * 4;
        int w_ = wgk >> 12, g = (wgk >> 10) & 3, k = wgk & 1023;
        ((float4*)ws)[i] = *(const float4*)(Whh + (size_t)(g * HH + blockIdx.x * 8 + w_) * HH + k);
    }
    for (int i = tid; i < 20480; i += 256) hs[i] = 0.0f;

    float creg = 0.0f;
    __syncthreads();

    for (int t = 0; t < LL; t++) {
        float2 xv;
        int xb = tid >> 4, xr = tid & 15, xg = xr >> 2, xj2 = (xr & 3) << 1;
        xv = *(const float2*)(Xg + (size_t)(t * NB + xb) * G4 + xg * HH + blockIdx.x * 8 + xj2);

        if (t > 0) {
            const float4* src = (const float4*)g_h[t & 1];
            for (int i = tid; i < 4096; i += 256) {
                float4 hv = __ldcg(src + i);
                int k = i >> 2, b4 = (i & 3) << 2;
                *(float4*)(hs + k * 20 + b4) = hv;
            }
        }
        xs[xj2 * 64 + xg * 16 + xb]       = xv.x;
        xs[(xj2 + 1) * 64 + xg * 16 + xb] = xv.y;
        __syncthreads();

        ull acc[4][8];
#pragma unroll
        for (int g = 0; g < 4; g++)
#pragma unroll
            for (int p = 0; p < 8; p++) acc[g][p] = 0ull;

        const float* wr = ws + wp * 4096;
#pragma unroll 8
        for (int i = 0; i < 32; i++) {
            int k = i * 32 + lane;
            ull W0 = pack2(wr[k]);
            ull W1 = pack2(wr[1024 + k]);
            ull W2 = pack2(wr[2048 + k]);
            ull W3 = pack2(wr[3072 + k]);
            const ulonglong2* hp = (const ulonglong2*)(hs + k * 20);
            ulonglong2 ha = hp[0], hb = hp[1], hc = hp[2], hd = hp[3];
            ffma2(acc[0][0], W0, ha.x); ffma2(acc[0][1], W0, ha.y);
            ffma2(acc[0][2], W0, hb.x); ffma2(acc[0][3], W0, hb.y);
            ffma2(acc[0][4], W0, hc.x); ffma2(acc[0][5], W0, hc.y);
            ffma2(acc[0][6], W0, hd.x); ffma2(acc[0][7], W0, hd.y);
            ffma2(acc[1][0], W1, ha.x); ffma2(acc[1][1], W1, ha.y);
            ffma2(acc[1][2], W1, hb.x); ffma2(acc[1][3], W1, hb.y);
            ffma2(acc[1][4], W1, hc.x); ffma2(acc[1][5], W1, hc.y);
            ffma2(acc[1][6], W1, hd.x); ffma2(acc[1][7], W1, hd.y);
            ffma2(acc[2][0], W2, ha.x); ffma2(acc[2][1], W2, ha.y);
            ffma2(acc[2][2], W2, hb.x); ffma2(acc[2][3], W2, hb.y);
            ffma2(acc[2][4], W2, hc.x); ffma2(acc[2][5], W2, hc.y);
            ffma2(acc[2][6], W2, hd.x); ffma2(acc[2][7], W2, hd.y);
            ffma2(acc[3][0], W3, ha.x); ffma2(acc[3][1], W3, ha.y);
            ffma2(acc[3][2], W3, hb.x); ffma2(acc[3][3], W3, hb.y);
            ffma2(acc[3][4], W3, hc.x); ffma2(acc[3][5], W3, hc.y);
            ffma2(acc[3][6], W3, hd.x); ffma2(acc[3][7], W3, hd.y);
        }

        ull* v = &acc[0][0];
#pragma unroll
        for (int m = 16; m >= 1; m >>= 1) {
            int half = m;
#pragma unroll
            for (int i = 0; i < 16; i++) {
                if (i < half) {
                    ull send = (lane & m) ? v[i] : v[i + half];
                    ull recv = __shfl_xor_sync(0xffffffffu, send, m);
                    ull keep = (lane & m) ? v[i + half] : v[i];
                    v[i] = fadd2(keep, recv);
                }
            }
        }
        {
            int g = lane >> 3, p = lane & 7;
            float lo, hi;
            unpack2(v[0], lo, hi);
            gs[wp * 64 + g * 16 + 2 * p]     = lo;
            gs[wp * 64 + g * 16 + 2 * p + 1] = hi;
        }
        __syncwarp();

        if (lane < 16) {
            const int b = lane;
            float gi = gs[wp * 64 +  0 + b] + xs[wp * 64 +  0 + b];
            float gf = gs[wp * 64 + 16 + b] + xs[wp * 64 + 16 + b];
            float gg = gs[wp * 64 + 32 + b] + xs[wp * 64 + 32 + b];
            float go = gs[wp * 64 + 48 + b] + xs[wp * 64 + 48 + b];
            float c = sigf(gf) * creg + sigf(gi) * tanhf(gg);
            float h = sigf(go) * tanhf(c);
            creg = c;
            __stcg(&g_h[(t + 1) & 1][j * 16 + b], h);
            if (mode == 0)
                g_H0[(size_t)(t * NB + b) * HH + j] = h;
            else
                Out[(size_t)b * (LL * HH) + (size_t)t * HH + j] = h;
        }

        if (t != LL - 1) grid_sync();
    }
}

// ---------------------------------------------------------------------------
extern "C" void kernel_launch(void* const* d_in, const int* in_sizes, int n_in,
                              void* d_out, int out_size)
{
    const int*   x    = nullptr;
    const float* emb  = nullptr;
    const float* wih0 = nullptr;
    const float* bias_[2] = {nullptr, nullptr};
    const float* w4[3] = {nullptr, nullptr, nullptr};
    int nbias = 0, nw = 0;
    for (int i = 0; i < n_in; i++) {
        long long sz = in_sizes[i];
        if (sz == (long long)NB * LL)             x = (const int*)d_in[i];
        else if (sz == (long long)VV * EE)        emb = (const float*)d_in[i];
        else if (sz == (long long)G4 * EE)        wih0 = (const float*)d_in[i];
        else if (sz == (long long)G4)             { if (nbias < 2) bias_[nbias++] = (const float*)d_in[i]; }
        else if (sz == (long long)G4 * HH)        { if (nw < 3) w4[nw++] = (const float*)d_in[i]; }
    }
    if (!x || !emb || !wih0 || nbias < 2 || nw < 3) {
        x = (const int*)d_in[0];
        emb = (const float*)d_in[1];
        wih0 = (const float*)d_in[2];
        w4[0] = (const float*)d_in[3];
        bias_[0] = (const float*)d_in[4];
        w4[1] = (const float*)d_in[5];
        w4[2] = (const float*)d_in[6];
        bias_[1] = (const float*)d_in[7];
    }
    const float* whh0 = w4[0];
    const float* b0   = bias_[0];
    const float* wih1 = w4[1];
    const float* whh1 = w4[2];
    const float* b1   = bias_[1];
    float* out = (float*)d_out;

    const int smem_rec = (32768 + 20480 + 512 + 512) * (int)sizeof(float);  // 217088 B
    cudaFuncSetAttribute(lstm_rec, cudaFuncAttributeMaxDynamicSharedMemorySize, smem_rec);

    dim3 ggrid(G4 / 128, MM / 128);  // (32, 16)

    gemm_tc<EE><<<ggrid, 256>>>(emb, x, wih0, b0, 0, 0);
    lstm_rec<<<RB, 256, smem_rec>>>(whh0, out, 0, 0);
    gemm_tc<HH><<<ggrid, 256>>>(emb, nullptr, wih1, b1, 1, 1);
    lstm_rec<<<RB, 256, smem_rec>>>(whh1, out, 1, 1);
}

// round 12
// speedup vs baseline: 1.0515x; 1.0085x over previous
#include <cuda_runtime.h>
#include <cuda_bf16.h>

// Problem dims  (V, E, H, N, L = 32000, 512, 1024, 16, 128)
#define VV 32000
#define NB 16
#define LL 128
#define EE 512
#define HH 1024
#define G4 4096
#define MM (NB*LL)
#define RB 128           // persistent recurrence CTAs (1/SM, co-resident)
#define NGRP 8
#define GSZ  16

// Scratch
__device__ __align__(16) float g_X0[(size_t)MM * G4];
__device__ __align__(16) float g_X1[(size_t)MM * G4];
__device__ __align__(16) float g_H0[(size_t)MM * HH];
__device__ __align__(16) float g_h[2][NB * HH];
// Monotonic barrier state: NEVER reset; all values derived from atomic returns.
__device__ __align__(16) unsigned g_grpm[NGRP * 64];   // group counters, 256B apart
__device__ unsigned g_rootm = 0;
__device__ unsigned g_genm  = 0;

__device__ __forceinline__ float sigf(float x) { return 1.0f / (1.0f + __expf(-x)); }

// ---- packed f32x2 helpers -------------------------------------------------
typedef unsigned long long ull;

__device__ __forceinline__ ull pack2(float x) {
    ull r; asm("mov.b64 %0, {%1, %1};" : "=l"(r) : "f"(x)); return r;
}
__device__ __forceinline__ void ffma2(ull& d, ull a, ull b) {
    asm("fma.rn.f32x2 %0, %1, %2, %0;" : "+l"(d) : "l"(a), "l"(b));
}
__device__ __forceinline__ ull fadd2(ull a, ull b) {
    ull d; asm("add.rn.f32x2 %0, %1, %2;" : "=l"(d) : "l"(a), "l"(b)); return d;
}
__device__ __forceinline__ void unpack2(ull v, float& lo, float& hi) {
    asm("mov.b64 {%0, %1}, %2;" : "=f"(lo), "=f"(hi) : "l"(v));
}

// ---- grid barrier: monotonic two-level tree, NO resets --------------------
// Instance n derived from arrival return (old>>4). Group completer
// (old&15)==15 arrives at root; root completer (ro&7)==7 bumps gen.
// Everyone else spins until gen >= n+1 (signed wrap-safe).
__device__ __forceinline__ void grid_sync() {
    __threadfence();
    __syncthreads();
    if (threadIdx.x == 0) {
        const int g = blockIdx.x >> 4;
        unsigned old = atomicAdd(&g_grpm[g * 64], 1u);
        unsigned n = old >> 4;                  // barrier instance
        bool released = false;
        if ((old & 15u) == 15u) {
            __threadfence();
            unsigned ro = atomicAdd(&g_rootm, 1u);
            if ((ro & 7u) == 7u) {
                __threadfence();
                atomicAdd(&g_genm, 1u);         // release: gen -> n+1
                released = true;
            }
        }
        if (!released) {
            while ((int)(((volatile unsigned*)&g_genm)[0] - (n + 1u)) < 0) { }
        }
        __threadfence();
    }
    __syncthreads();
}

// ---- bf16 hi/lo split pack ------------------------------------------------
__device__ __forceinline__ void cvt_pair(float x0, float x1, unsigned& hi, unsigned& lo) {
    __nv_bfloat16 h0 = __float2bfloat16(x0);
    __nv_bfloat16 h1 = __float2bfloat16(x1);
    float r0 = x0 - __bfloat162float(h0);
    float r1 = x1 - __bfloat162float(h1);
    __nv_bfloat162 hp = __halves2bfloat162(h0, h1);
    __nv_bfloat162 lp = __halves2bfloat162(__float2bfloat16(r0), __float2bfloat16(r1));
    hi = *(unsigned*)&hp;
    lo = *(unsigned*)&lp;
}

#define MMA4(d, a, b0r, b1r) \
    asm volatile("mma.sync.aligned.m16n8k16.row.col.f32.bf16.bf16.f32 " \
        "{%0,%1,%2,%3}, {%4,%5,%6,%7}, {%8,%9}, {%0,%1,%2,%3};" \
        : "+f"((d)[0]), "+f"((d)[1]), "+f"((d)[2]), "+f"((d)[3]) \
        : "r"((a)[0]), "r"((a)[1]), "r"((a)[2]), "r"((a)[3]), "r"(b0r), "r"(b1r))

// ---------------------------------------------------------------------------
// Tensor-core GEMM: C[m][r] = sum_k A[m][k]*B[r][k] + bias[r].
// bf16 hi/lo split, 3 passes (hi*hi + hi*lo + lo*hi), fp32 accum.
// Tile 128x128, 8 warps (4 along m x 2 along n), warp tile 32m x 64n.
// Both operands k-contiguous -> direct lds.b32 fragment loads, no ldmatrix.
// ---------------------------------------------------------------------------
template <int K>
__global__ __launch_bounds__(256) void gemm_tc(
    const float* __restrict__ Aext,
    const int*   __restrict__ tokens,
    const float* __restrict__ Bw,
    const float* __restrict__ bias,
    int a_sel, int c_sel)
{
    __shared__ __align__(16) unsigned sAhi[128 * 9];
    __shared__ __align__(16) unsigned sAlo[128 * 9];
    __shared__ __align__(16) unsigned sBhi[128 * 9];
    __shared__ __align__(16) unsigned sBlo[128 * 9];

    float* C = c_sel ? g_X1 : g_X0;
    const int bm = blockIdx.y, br = blockIdx.x;
    const int tid = threadIdx.x, lane = tid & 31, wid = tid >> 5;

    // loader: thread t handles row ra = t>>1, k-offset kc = (t&1)*8 (8 floats)
    const int ra = tid >> 1;
    const int kc = (tid & 1) * 8;

    const float* arow;
    if (tokens) {
        int gm = bm * 128 + ra;
        int tok = tokens[(gm & (NB - 1)) * LL + (gm >> 4)];
        tok = min(max(tok, 0), VV - 1);
        arow = Aext + (size_t)tok * K + kc;
    } else {
        const float* A = a_sel ? g_H0 : Aext;
        arow = A + (size_t)(bm * 128 + ra) * K + kc;
    }
    const float* brow = Bw + (size_t)(br * 128 + ra) * K + kc;

    const int wm = (wid & 3) * 32;      // warp m offset
    const int wn = (wid >> 2) * 64;     // warp n offset
    const int gid = lane >> 2, qc = lane & 3;

    float acc[2][8][4];
#pragma unroll
    for (int mi = 0; mi < 2; mi++)
#pragma unroll
        for (int j = 0; j < 8; j++)
#pragma unroll
            for (int e = 0; e < 4; e++) acc[mi][j][e] = 0.0f;

    // helper lambda-ish: convert 8 floats -> 4 hi/lo u32 pairs and store
#define STCVT(dsthi, dstlo, v0, v1)  do {                                   \
        unsigned h_, l_;                                                    \
        cvt_pair((v0).x, (v0).y, h_, l_); dsthi[ra*9 + kc/2 + 0] = h_; dstlo[ra*9 + kc/2 + 0] = l_; \
        cvt_pair((v0).z, (v0).w, h_, l_); dsthi[ra*9 + kc/2 + 1] = h_; dstlo[ra*9 + kc/2 + 1] = l_; \
        cvt_pair((v1).x, (v1).y, h_, l_); dsthi[ra*9 + kc/2 + 2] = h_; dstlo[ra*9 + kc/2 + 2] = l_; \
        cvt_pair((v1).z, (v1).w, h_, l_); dsthi[ra*9 + kc/2 + 3] = h_; dstlo[ra*9 + kc/2 + 3] = l_; \
    } while (0)

    // prologue: tile 0
    {
        float4 av0 = *(const float4*)(arow);
        float4 av1 = *(const float4*)(arow + 4);
        float4 bv0 = *(const float4*)(brow);
        float4 bv1 = *(const float4*)(brow + 4);
        STCVT(sAhi, sAlo, av0, av1);
        STCVT(sBhi, sBlo, bv0, bv1);
    }
    __syncthreads();

#pragma unroll 1
    for (int k0 = 0; k0 < K; k0 += 16) {
        const bool more = (k0 + 16) < K;
        float4 nav0, nav1, nbv0, nbv1;
        if (more) {
            nav0 = *(const float4*)(arow + k0 + 16);
            nav1 = *(const float4*)(arow + k0 + 20);
            nbv0 = *(const float4*)(brow + k0 + 16);
            nbv1 = *(const float4*)(brow + k0 + 20);
        }

        // A fragments for both m16 tiles (hi and lo)
        unsigned ahi[2][4], alo[2][4];
#pragma unroll
        for (int mi = 0; mi < 2; mi++) {
            int r0 = (wm + mi * 16 + gid) * 9;
            int r8 = r0 + 8 * 9;
            ahi[mi][0] = sAhi[r0 + qc];     ahi[mi][1] = sAhi[r8 + qc];
            ahi[mi][2] = sAhi[r0 + qc + 4]; ahi[mi][3] = sAhi[r8 + qc + 4];
            alo[mi][0] = sAlo[r0 + qc];     alo[mi][1] = sAlo[r8 + qc];
            alo[mi][2] = sAlo[r0 + qc + 4]; alo[mi][3] = sAlo[r8 + qc + 4];
        }

#pragma unroll
        for (int j = 0; j < 8; j++) {
            int rb = (wn + j * 8 + gid) * 9;
            unsigned bh0 = sBhi[rb + qc], bh1 = sBhi[rb + qc + 4];
            unsigned bl0 = sBlo[rb + qc], bl1 = sBlo[rb + qc + 4];
#pragma unroll
            for (int mi = 0; mi < 2; mi++) {
                MMA4(acc[mi][j], ahi[mi], bh0, bh1);
                MMA4(acc[mi][j], ahi[mi], bl0, bl1);
                MMA4(acc[mi][j], alo[mi], bh0, bh1);
            }
        }

        if (more) {
            __syncthreads();           // all fragment reads done
            STCVT(sAhi, sAlo, nav0, nav1);
            STCVT(sBhi, sBlo, nbv0, nbv1);
            __syncthreads();
        }
    }
#undef STCVT

    // epilogue: c0,c1 = (row gid, cols 2qc,2qc+1); c2,c3 = row gid+8
#pragma unroll
    for (int j = 0; j < 8; j++) {
        int gc = br * 128 + wn + j * 8 + qc * 2;
        float b0v = bias[gc], b1v = bias[gc + 1];
#pragma unroll
        for (int mi = 0; mi < 2; mi++) {
            int gm0 = bm * 128 + wm + mi * 16 + gid;
            float2 o0 = make_float2(acc[mi][j][0] + b0v, acc[mi][j][1] + b1v);
            float2 o1 = make_float2(acc[mi][j][2] + b0v, acc[mi][j][3] + b1v);
            *(float2*)(C + (size_t)gm0 * G4 + gc)       = o0;
            *(float2*)(C + (size_t)(gm0 + 8) * G4 + gc) = o1;
        }
    }
}

// ---------------------------------------------------------------------------
// Persistent LSTM recurrence: 128 CTAs x 256 thr, all 128 steps in one launch.
// ---------------------------------------------------------------------------
__global__ __launch_bounds__(256) void lstm_rec(
    const float* __restrict__ Whh,
    float* __restrict__ Out,
    int xsel, int mode)
{
    extern __shared__ __align__(16) float sm[];
    float* ws = sm;                    // 32768 floats: ws[w][g][k]
    float* hs = sm + 32768;            // 20480 floats: h padded [k][20]
    float* gs = hs + 20480;            // 512: reduced gates
    float* xs = gs + 512;              // 512: staged X slice

    const float* Xg = xsel ? g_X1 : g_X0;
    const int tid = threadIdx.x, lane = tid & 31, wp = tid >> 5;
    const int j = blockIdx.x * 8 + wp;

    for (int i = tid; i < 8192; i += 256) {
        int wgk = i * 4;
        int w_ = wgk >> 12, g = (wgk >> 10) & 3, k = wgk & 1023;
        ((float4*)ws)[i] = *(const float4*)(Whh + (size_t)(g * HH + blockIdx.x * 8 + w_) * HH + k);
    }
    for (int i = tid; i < 20480; i += 256) hs[i] = 0.0f;

    float creg = 0.0f;
    __syncthreads();

    for (int t = 0; t < LL; t++) {
        float2 xv;
        int xb = tid >> 4, xr = tid & 15, xg = xr >> 2, xj2 = (xr & 3) << 1;
        xv = *(const float2*)(Xg + (size_t)(t * NB + xb) * G4 + xg * HH + blockIdx.x * 8 + xj2);

        if (t > 0) {
            const float4* src = (const float4*)g_h[t & 1];
            for (int i = tid; i < 4096; i += 256) {
                float4 hv = __ldcg(src + i);
                int k = i >> 2, b4 = (i & 3) << 2;
                *(float4*)(hs + k * 20 + b4) = hv;
            }
        }
        xs[xj2 * 64 + xg * 16 + xb]       = xv.x;
        xs[(xj2 + 1) * 64 + xg * 16 + xb] = xv.y;
        __syncthreads();

        ull acc[4][8];
#pragma unroll
        for (int g = 0; g < 4; g++)
#pragma unroll
            for (int p = 0; p < 8; p++) acc[g][p] = 0ull;

        const float* wr = ws + wp * 4096;
#pragma unroll 8
        for (int i = 0; i < 32; i++) {
            int k = i * 32 + lane;
            ull W0 = pack2(wr[k]);
            ull W1 = pack2(wr[1024 + k]);
            ull W2 = pack2(wr[2048 + k]);
            ull W3 = pack2(wr[3072 + k]);
            const ulonglong2* hp = (const ulonglong2*)(hs + k * 20);
            ulonglong2 ha = hp[0], hb = hp[1], hc = hp[2], hd = hp[3];
            ffma2(acc[0][0], W0, ha.x); ffma2(acc[0][1], W0, ha.y);
            ffma2(acc[0][2], W0, hb.x); ffma2(acc[0][3], W0, hb.y);
            ffma2(acc[0][4], W0, hc.x); ffma2(acc[0][5], W0, hc.y);
            ffma2(acc[0][6], W0, hd.x); ffma2(acc[0][7], W0, hd.y);
            ffma2(acc[1][0], W1, ha.x); ffma2(acc[1][1], W1, ha.y);
            ffma2(acc[1][2], W1, hb.x); ffma2(acc[1][3], W1, hb.y);
            ffma2(acc[1][4], W1, hc.x); ffma2(acc[1][5], W1, hc.y);
            ffma2(acc[1][6], W1, hd.x); ffma2(acc[1][7], W1, hd.y);
            ffma2(acc[2][0], W2, ha.x); ffma2(acc[2][1], W2, ha.y);
            ffma2(acc[2][2], W2, hb.x); ffma2(acc[2][3], W2, hb.y);
            ffma2(acc[2][4], W2, hc.x); ffma2(acc[2][5], W2, hc.y);
            ffma2(acc[2][6], W2, hd.x); ffma2(acc[2][7], W2, hd.y);
            ffma2(acc[3][0], W3, ha.x); ffma2(acc[3][1], W3, ha.y);
            ffma2(acc[3][2], W3, hb.x); ffma2(acc[3][3], W3, hb.y);
            ffma2(acc[3][4], W3, hc.x); ffma2(acc[3][5], W3, hc.y);
            ffma2(acc[3][6], W3, hd.x); ffma2(acc[3][7], W3, hd.y);
        }

        ull* v = &acc[0][0];
#pragma unroll
        for (int m = 16; m >= 1; m >>= 1) {
            int half = m;
#pragma unroll
            for (int i = 0; i < 16; i++) {
                if (i < half) {
                    ull send = (lane & m) ? v[i] : v[i + half];
                    ull recv = __shfl_xor_sync(0xffffffffu, send, m);
                    ull keep = (lane & m) ? v[i + half] : v[i];
                    v[i] = fadd2(keep, recv);
                }
            }
        }
        {
            int g = lane >> 3, p = lane & 7;
            float lo, hi;
            unpack2(v[0], lo, hi);
            gs[wp * 64 + g * 16 + 2 * p]     = lo;
            gs[wp * 64 + g * 16 + 2 * p + 1] = hi;
        }
        __syncwarp();

        if (lane < 16) {
            const int b = lane;
            float gi = gs[wp * 64 +  0 + b] + xs[wp * 64 +  0 + b];
            float gf = gs[wp * 64 + 16 + b] + xs[wp * 64 + 16 + b];
            float gg = gs[wp * 64 + 32 + b] + xs[wp * 64 + 32 + b];
            float go = gs[wp * 64 + 48 + b] + xs[wp * 64 + 48 + b];
            float c = sigf(gf) * creg + sigf(gi) * tanhf(gg);
            float h = sigf(go) * tanhf(c);
            creg = c;
            __stcg(&g_h[(t + 1) & 1][j * 16 + b], h);
            if (mode == 0)
                g_H0[(size_t)(t * NB + b) * HH + j] = h;
            else
                Out[(size_t)b * (LL * HH) + (size_t)t * HH + j] = h;
        }

        if (t != LL - 1) grid_sync();
    }
}

// ---------------------------------------------------------------------------
extern "C" void kernel_launch(void* const* d_in, const int* in_sizes, int n_in,
                              void* d_out, int out_size)
{
    const int*   x    = nullptr;
    const float* emb  = nullptr;
    const float* wih0 = nullptr;
    const float* bias_[2] = {nullptr, nullptr};
    const float* w4[3] = {nullptr, nullptr, nullptr};
    int nbias = 0, nw = 0;
    for (int i = 0; i < n_in; i++) {
        long long sz = in_sizes[i];
        if (sz == (long long)NB * LL)             x = (const int*)d_in[i];
        else if (sz == (long long)VV * EE)        emb = (const float*)d_in[i];
        else if (sz == (long long)G4 * EE)        wih0 = (const float*)d_in[i];
        else if (sz == (long long)G4)             { if (nbias < 2) bias_[nbias++] = (const float*)d_in[i]; }
        else if (sz == (long long)G4 * HH)        { if (nw < 3) w4[nw++] = (const float*)d_in[i]; }
    }
    if (!x || !emb || !wih0 || nbias < 2 || nw < 3) {
        x = (const int*)d_in[0];
        emb = (const float*)d_in[1];
        wih0 = (const float*)d_in[2];
        w4[0] = (const float*)d_in[3];
        bias_[0] = (const float*)d_in[4];
        w4[1] = (const float*)d_in[5];
        w4[2] = (const float*)d_in[6];
        bias_[1] = (const float*)d_in[7];
    }
    const float* whh0 = w4[0];
    const float* b0   = bias_[0];
    const float* wih1 = w4[1];
    const float* whh1 = w4[2];
    const float* b1   = bias_[1];
    float* out = (float*)d_out;

    const int smem_rec = (32768 + 20480 + 512 + 512) * (int)sizeof(float);  // 217088 B
    cudaFuncSetAttribute(lstm_rec, cudaFuncAttributeMaxDynamicSharedMemorySize, smem_rec);

    dim3 ggrid(G4 / 128, MM / 128);  // (32, 16)

    gemm_tc<EE><<<ggrid, 256>>>(emb, x, wih0, b0, 0, 0);
    lstm_rec<<<RB, 256, smem_rec>>>(whh0, out, 0, 0);
    gemm_tc<HH><<<ggrid, 256>>>(emb, nullptr, wih1, b1, 1, 1);
    lstm_rec<<<RB, 256, smem_rec>>>(whh1, out, 1, 1);
}